// round 13
// baseline (speedup 1.0000x reference)
#include <cuda_runtime.h>
#include <cstdint>

#define BS 256
#define D  2048
#define H  1024
#define C  200
#define NC 112

// ---------------- scratch (static device allocations only) ----------------
__device__ float g_y1[C * H];
__device__ float g_c1[2 * NC * H];
__device__ float g_hxy[BS * H];
__device__ float g_hxc[BS * H];
__device__ float g_pn[NC * H];
__device__ float g_pd[NC * H];
__device__ float g_cproj[BS * H];
__device__ int   g_cp_done;

// ---------------- packed f32x2 helpers -------------------------------------
__device__ __forceinline__ uint64_t pack2(float x, float y) {
    uint64_t r;
    asm("mov.b64 %0, {%1, %2};" : "=l"(r) : "f"(x), "f"(y));
    return r;
}
__device__ __forceinline__ void fma2(uint64_t& d, uint64_t a, uint64_t b) {
    asm("fma.rn.f32x2 %0, %1, %2, %0;" : "+l"(d) : "l"(a), "l"(b));
}
__device__ __forceinline__ float2 unpack2(uint64_t v) {
    float2 f;
    asm("mov.b64 {%0, %1}, %2;" : "=f"(f.x), "=f"(f.y) : "l"(v));
    return f;
}

// ---------------- JAX threefry2x32 (partitionable semantics) --------------
__device__ __forceinline__ uint32_t rotl32(uint32_t v, int r) {
    return (v << r) | (v >> (32 - r));
}

__device__ __forceinline__ void tf2x32(uint32_t k0, uint32_t k1,
                                       uint32_t x0, uint32_t x1,
                                       uint32_t& o0, uint32_t& o1) {
    uint32_t ks2 = k0 ^ k1 ^ 0x1BD11BDAu;
    x0 += k0; x1 += k1;
#define TF_R(r) { x0 += x1; x1 = rotl32(x1, r); x1 ^= x0; }
    TF_R(13) TF_R(15) TF_R(26) TF_R(6)   x0 += k1;  x1 += ks2 + 1u;
    TF_R(17) TF_R(29) TF_R(16) TF_R(24)  x0 += ks2; x1 += k0 + 2u;
    TF_R(13) TF_R(15) TF_R(26) TF_R(6)   x0 += k0;  x1 += k1 + 3u;
    TF_R(17) TF_R(29) TF_R(16) TF_R(24)  x0 += k1;  x1 += ks2 + 4u;
    TF_R(13) TF_R(15) TF_R(26) TF_R(6)   x0 += ks2; x1 += k0 + 5u;
#undef TF_R
    o0 = x0; o1 = x1;
}

__device__ __forceinline__ bool drop_keep(uint32_t ka, uint32_t kb, uint32_t idx) {
    uint32_t a, b;
    tf2x32(ka, kb, 0u, idx, a, b);
    uint32_t bits = a ^ b;
    float u = __uint_as_float((bits >> 9) | 0x3F800000u) - 1.0f;
    return u < 0.8f;
}

// ---------------- shared-memory overlays ----------------------------------
struct SmemFc1  { float As[32][68]; float Bs[32][68]; };                   // 17408 B
struct SmemNorm { float red[256]; };
struct SmemCp   { float As[16][64]; float Bs[16][64]; float base[64]; };
struct SmemXY   { float Hs[64][17]; float Ys[64][33]; float ws[64]; };
struct SmemXC   { float Hs[32][33]; float Cs[32][17]; float Ws[32][9]; };

#define SMEM_BYTES 17408

// ---------------- part: 1 + l2norm of one row ------------------------------
__device__ void part_norm(char* smem, int r,
                          const float* __restrict__ ye,
                          const float* __restrict__ ce) {
    SmemNorm& s = *reinterpret_cast<SmemNorm*>(smem);
    const float* src;
    float* dst;
    if (r < C) { src = ye + (size_t)r * H;        dst = g_y1 + (size_t)r * H; }
    else       { src = ce + (size_t)(r - C) * H;  dst = g_c1 + (size_t)(r - C) * H; }
    int t = threadIdx.x;
    float4 v = *reinterpret_cast<const float4*>(&src[t * 4]);
    s.red[t] = v.x * v.x + v.y * v.y + v.z * v.z + v.w * v.w;
    __syncthreads();
    for (int o = 128; o; o >>= 1) {
        if (t < o) s.red[t] += s.red[t + o];
        __syncthreads();
    }
    float n = fmaxf(sqrtf(s.red[0]), 1e-12f);
    dst[t * 4 + 0] = 1.0f + v.x / n;
    dst[t * 4 + 1] = 1.0f + v.y / n;
    dst[t * 4 + 2] = 1.0f + v.z / n;
    dst[t * 4 + 3] = 1.0f + v.w / n;
}

// ---------------- part: fc1 GEMM (f32x2, 64x64 tile) + bias + dropout ------
__device__ void part_fc1(char* smem, int which, int n0, int m0,
                         const float* __restrict__ x,
                         const float* __restrict__ W,
                         const float* __restrict__ B,
                         float* __restrict__ out) {
    SmemFc1& s = *reinterpret_cast<SmemFc1*>(smem);
    const int tid = threadIdx.x;
    const int tx = tid % 16, ty = tid / 16;
    const int lr = tid / 4;
    const int lc = (tid % 4) * 8;
    uint64_t acc[4][2] = {};
    for (int k0 = 0; k0 < D; k0 += 32) {
        {
            const float* xr = &x[(size_t)(m0 + lr) * D + k0 + lc];
            float4 a0 = *reinterpret_cast<const float4*>(xr);
            float4 a1 = *reinterpret_cast<const float4*>(xr + 4);
            const float* wr = &W[(size_t)(n0 + lr) * D + k0 + lc];
            float4 b0 = *reinterpret_cast<const float4*>(wr);
            float4 b1 = *reinterpret_cast<const float4*>(wr + 4);
            s.As[lc + 0][lr] = a0.x; s.As[lc + 1][lr] = a0.y;
            s.As[lc + 2][lr] = a0.z; s.As[lc + 3][lr] = a0.w;
            s.As[lc + 4][lr] = a1.x; s.As[lc + 5][lr] = a1.y;
            s.As[lc + 6][lr] = a1.z; s.As[lc + 7][lr] = a1.w;
            s.Bs[lc + 0][lr] = b0.x; s.Bs[lc + 1][lr] = b0.y;
            s.Bs[lc + 2][lr] = b0.z; s.Bs[lc + 3][lr] = b0.w;
            s.Bs[lc + 4][lr] = b1.x; s.Bs[lc + 5][lr] = b1.y;
            s.Bs[lc + 6][lr] = b1.z; s.Bs[lc + 7][lr] = b1.w;
        }
        __syncthreads();
#pragma unroll
        for (int kk = 0; kk < 32; kk++) {
            float4 a = *reinterpret_cast<const float4*>(&s.As[kk][ty * 4]);
            float4 b = *reinterpret_cast<const float4*>(&s.Bs[kk][tx * 4]);
            uint64_t b01 = pack2(b.x, b.y);
            uint64_t b23 = pack2(b.z, b.w);
            uint64_t ap;
            ap = pack2(a.x, a.x); fma2(acc[0][0], ap, b01); fma2(acc[0][1], ap, b23);
            ap = pack2(a.y, a.y); fma2(acc[1][0], ap, b01); fma2(acc[1][1], ap, b23);
            ap = pack2(a.z, a.z); fma2(acc[2][0], ap, b01); fma2(acc[2][1], ap, b23);
            ap = pack2(a.w, a.w); fma2(acc[3][0], ap, b01); fma2(acc[3][1], ap, b23);
        }
        __syncthreads();
    }
    uint32_t ka, kb;
    tf2x32(0u, 42u, 0u, (uint32_t)which, ka, kb);
#pragma unroll
    for (int i = 0; i < 4; i++) {
        int b = m0 + ty * 4 + i;
#pragma unroll
        for (int jp = 0; jp < 2; jp++) {
            float2 v = unpack2(acc[i][jp]);
            int col = n0 + tx * 4 + jp * 2;
            float h0 = v.x + B[col];
            float h1 = v.y + B[col + 1];
            uint32_t i0 = (uint32_t)(b * H + col);
            out[(size_t)b * H + col]     = drop_keep(ka, kb, i0)      ? h0 / 0.8f : 0.0f;
            out[(size_t)b * H + col + 1] = drop_keep(ka, kb, i0 + 1u) ? h1 / 0.8f : 0.0f;
        }
    }
}

// ---------------- part: stream concept_proj_w once (register-resident e) ----
// R9-proven: warp = 4 sequential rows, 8 LDG.128 batches, batched butterfly.
__device__ void part_pnd(int n, int jg,
                         const float* __restrict__ ce,
                         const float* __restrict__ W) {
    const int tid = threadIdx.x;
    const int w = tid >> 5, lane = tid & 31;
    const int jbase = jg * 32 + w * 4;
    const size_t rs = (size_t)NC * H;
    float4 ep[8], en[8];
    {
        const float* epg = ce + (size_t)n * H + lane * 4;
        const float* eng = ce + (size_t)(NC + n) * H + lane * 4;
#pragma unroll
        for (int c = 0; c < 8; c++) {
            ep[c] = *reinterpret_cast<const float4*>(&epg[c * 128]);
            en[c] = *reinterpret_cast<const float4*>(&eng[c * 128]);
        }
    }
    const float* Wr = W + (size_t)jbase * rs + (size_t)n * H + lane * 4;
    float ap[4], an[4];
#pragma unroll
    for (int r = 0; r < 4; r++) { ap[r] = 0.f; an[r] = 0.f; }
#pragma unroll 1
    for (int r = 0; r < 4; r++) {
        const float* Wp = Wr + (size_t)r * rs;
        float4 wv[8];
#pragma unroll
        for (int c = 0; c < 8; c++)
            wv[c] = *reinterpret_cast<const float4*>(&Wp[c * 128]);
        float a = 0.f, b = 0.f;
#pragma unroll
        for (int c = 0; c < 8; c++) {
            a += wv[c].x * ep[c].x + wv[c].y * ep[c].y + wv[c].z * ep[c].z + wv[c].w * ep[c].w;
            b += wv[c].x * en[c].x + wv[c].y * en[c].y + wv[c].z * en[c].z + wv[c].w * en[c].w;
        }
        ap[r] = a; an[r] = b;
    }
#pragma unroll
    for (int off = 16; off; off >>= 1) {
#pragma unroll
        for (int r = 0; r < 4; r++) {
            ap[r] += __shfl_xor_sync(0xFFFFFFFFu, ap[r], off);
            an[r] += __shfl_xor_sync(0xFFFFFFFFu, an[r], off);
        }
    }
    if (lane == 0) {
#pragma unroll
        for (int r = 0; r < 4; r++) {
            g_pn[n * H + jbase + r] = an[r];
            g_pd[n * H + jbase + r] = ap[r] - an[r];
        }
    }
}

// ---------------- part: c_proj = (bias + sum_n pn) + gt @ pd ----------------
__device__ void part_cproj(char* smem, int j0, int m0,
                           const int* __restrict__ cgt,
                           const float* __restrict__ bias) {
    SmemCp& s = *reinterpret_cast<SmemCp*>(smem);
    const int tid = threadIdx.x;
    {
        int col = j0 + (tid & 63);
        if (tid < 64) s.base[tid] = bias[col];
        __syncthreads();
        int nb = (tid >> 6) * 28;
        float part = 0.f;
#pragma unroll 4
        for (int n = nb; n < nb + 28; n++) part += g_pn[n * H + col];
        atomicAdd(&s.base[tid & 63], part);
    }
    const int tx = tid % 16, ty = tid / 16;
    float acc[4][4] = {};
    for (int k0 = 0; k0 < NC; k0 += 16) {
        __syncthreads();
        {
            int r = tid / 4;
            int c = (tid % 4) * 4;
            int b = m0 + r;
#pragma unroll
            for (int q = 0; q < 4; q++)
                s.As[c + q][r] = (cgt[(size_t)b * NC + k0 + c + q] == 1) ? 1.0f : 0.0f;
        }
        {
            int kk = tid / 16;
            int j4 = (tid % 16) * 4;
            float4 v = *reinterpret_cast<const float4*>(&g_pd[(size_t)(k0 + kk) * H + j0 + j4]);
            *reinterpret_cast<float4*>(&s.Bs[kk][j4]) = v;
        }
        __syncthreads();
#pragma unroll
        for (int kk = 0; kk < 16; kk++) {
            float4 a = *reinterpret_cast<const float4*>(&s.As[kk][ty * 4]);
            float4 b = *reinterpret_cast<const float4*>(&s.Bs[kk][tx * 4]);
            float av[4] = {a.x, a.y, a.z, a.w};
            float bv[4] = {b.x, b.y, b.z, b.w};
#pragma unroll
            for (int i = 0; i < 4; i++)
#pragma unroll
                for (int j = 0; j < 4; j++)
                    acc[i][j] = fmaf(av[i], bv[j], acc[i][j]);
        }
    }
#pragma unroll
    for (int i = 0; i < 4; i++) {
        int b = m0 + ty * 4 + i;
#pragma unroll
        for (int j = 0; j < 4; j++) {
            int col = j0 + tx * 4 + j;
            g_cproj[(size_t)b * H + col] = acc[i][j] + s.base[tx * 4 + j];
        }
    }
    // release: this cproj tile is complete
    __syncthreads();
    __threadfence();
    if (tid == 0) atomicAdd(&g_cp_done, 1);
}

// ---------------- part: xy / cy energy (32 c x 16 b tile, 64-k chunks) ------
__device__ void part_xycy(char* smem, int c0, int b0,
                          const float* __restrict__ A,
                          const float* __restrict__ clsw,
                          float bias,
                          float* __restrict__ out) {
    SmemXY& s = *reinterpret_cast<SmemXY*>(smem);
    const int tid = threadIdx.x;
    const int tx = tid % 16;
    const int ty = tid / 16;
    float acc0 = 0.f, acc1 = 0.f;
    for (int k0 = 0; k0 < H; k0 += 64) {
        {
            int row = tid / 16, ko = (tid % 16) * 4;
            float4 v = *reinterpret_cast<const float4*>(&A[(size_t)(b0 + row) * H + k0 + ko]);
            s.Hs[ko + 0][row] = v.x; s.Hs[ko + 1][row] = v.y;
            s.Hs[ko + 2][row] = v.z; s.Hs[ko + 3][row] = v.w;
        }
        {
            int lr = tid / 8, lc = (tid % 8) * 4;
            int cr = c0 + lr; if (cr > C - 1) cr = C - 1;
            const float* yr = &g_y1[(size_t)cr * H + k0];
            float4 u = *reinterpret_cast<const float4*>(&yr[lc]);
            s.Ys[lc + 0][lr] = u.x; s.Ys[lc + 1][lr] = u.y;
            s.Ys[lc + 2][lr] = u.z; s.Ys[lc + 3][lr] = u.w;
            float4 u2 = *reinterpret_cast<const float4*>(&yr[32 + lc]);
            s.Ys[32 + lc + 0][lr] = u2.x; s.Ys[32 + lc + 1][lr] = u2.y;
            s.Ys[32 + lc + 2][lr] = u2.z; s.Ys[32 + lc + 3][lr] = u2.w;
        }
        if (tid < 64) s.ws[tid] = clsw[k0 + tid];
        __syncthreads();
#pragma unroll
        for (int kk = 0; kk < 64; kk++) {
            float h = s.Hs[kk][ty];
            float y0 = s.Ys[kk][tx * 2 + 0];
            float y1 = s.Ys[kk][tx * 2 + 1];
            float w = s.ws[kk];
            acc0 = fmaf(fmaxf(h * y0, 0.f), w, acc0);
            acc1 = fmaf(fmaxf(h * y1, 0.f), w, acc1);
        }
        __syncthreads();
    }
    int b = b0 + ty;
    int c = c0 + tx * 2;
    if (c < C)     out[(size_t)b * C + c]     = acc0 + bias;
    if (c + 1 < C) out[(size_t)b * C + c + 1] = acc1 + bias;
}

// ---------------- part: xc energy -------------------------------------------
__device__ void part_xc(char* smem, int n0, int b0,
                        const float* __restrict__ xcw,
                        const float* __restrict__ xcb,
                        float* __restrict__ out) {
    SmemXC& s = *reinterpret_cast<SmemXC*>(smem);
    const int tid = threadIdx.x;
    const int tx = tid % 8;
    const int ty = tid / 8;
    const int lr = tid / 8;
    const int lc = (tid % 8) * 4;
    float acc0 = 0.f, acc1 = 0.f;
    for (int k0 = 0; k0 < H; k0 += 32) {
        {
            float4 v = *reinterpret_cast<const float4*>(&g_hxc[(size_t)(b0 + lr) * H + k0 + lc]);
            s.Hs[lc + 0][lr] = v.x; s.Hs[lc + 1][lr] = v.y;
            s.Hs[lc + 2][lr] = v.z; s.Hs[lc + 3][lr] = v.w;
        }
        {
            int loc = tid / 16;
            int kk = (tid % 16) * 2;
            int nl = loc >> 1, sx = loc & 1;
            int row = sx * NC + (n0 + nl);
            float2 v = *reinterpret_cast<const float2*>(&g_c1[(size_t)row * H + k0 + kk]);
            s.Cs[kk + 0][nl * 2 + sx] = v.x;
            s.Cs[kk + 1][nl * 2 + sx] = v.y;
        }
        {
            int nl = tid / 32;
            int kk = tid % 32;
            s.Ws[kk][nl] = xcw[(size_t)(n0 + nl) * H + k0 + kk];
        }
        __syncthreads();
#pragma unroll
        for (int kk = 0; kk < 32; kk++) {
            float h = s.Hs[kk][ty];
            float w = s.Ws[kk][tx];
            float cp = s.Cs[kk][tx * 2 + 0];
            float cn = s.Cs[kk][tx * 2 + 1];
            acc0 = fmaf(fmaxf(h * cp, 0.f), w, acc0);
            acc1 = fmaf(fmaxf(h * cn, 0.f), w, acc1);
        }
        __syncthreads();
    }
    int b = b0 + ty, n = n0 + tx;
    float bb = xcb[n];
    size_t base = (size_t)(2 * BS * C) + (size_t)b * (NC * 2) + n * 2;
    out[base + 0] = acc0 + bb;
    out[base + 1] = acc1 + bb;
}

// ================= launch 1: fc1 + norm + pnd (overlapped) ==================
#define L1_FC1   128
#define L1_NORM  (C + 2 * NC)                 // 424
#define L1_PND   (NC * 32)                    // 3584
#define L1_GRID  (L1_FC1 + L1_NORM + L1_PND)

__global__ __launch_bounds__(256, 2) void k_main(const float* __restrict__ x,
                                                 const float* __restrict__ ye,
                                                 const float* __restrict__ ce,
                                                 const float* __restrict__ w0,
                                                 const float* __restrict__ b0,
                                                 const float* __restrict__ w1,
                                                 const float* __restrict__ b1,
                                                 const float* __restrict__ cpw) {
    __shared__ __align__(16) char smem[SMEM_BYTES];
    int bid = blockIdx.x;
    if (bid == 0 && threadIdx.x == 0) g_cp_done = 0;   // reset gate for k_mid
    if (bid < L1_FC1) {
        int which = bid >> 6;
        int rem = bid & 63;
        part_fc1(smem, which, (rem % 16) * 64, (rem / 16) * 64, x,
                 which ? w1 : w0, which ? b1 : b0, which ? g_hxc : g_hxy);
    } else if (bid < L1_FC1 + L1_NORM) {
        part_norm(smem, bid - L1_FC1, ye, ce);
    } else {
        int p = bid - (L1_FC1 + L1_NORM);
        part_pnd(p % NC, p / NC, ce, cpw);
    }
}

// ====== launch 2: cproj + xy-energy + xc-energy + cy-energy (gated) =========
#define L2_CP   (16 * 4)              // 64
#define L2_XY   (7 * 16)              // 112
#define L2_XC   (14 * 8)              // 112
#define L2_CY   (7 * 16)              // 112
#define L2_GRID (L2_CP + L2_XY + L2_XC + L2_CY)   // 400 (all co-resident)

__global__ __launch_bounds__(256) void k_mid(const int* __restrict__ cgt,
                                             const float* __restrict__ cpb,
                                             const float* __restrict__ clsxy_w,
                                             const float* __restrict__ clsxy_b,
                                             const float* __restrict__ clscy_w,
                                             const float* __restrict__ clscy_b,
                                             const float* __restrict__ xcw,
                                             const float* __restrict__ xcb,
                                             float* __restrict__ out) {
    __shared__ __align__(16) char smem[SMEM_BYTES];
    int bid = blockIdx.x;
    if (bid < L2_CP) {
        part_cproj(smem, (bid % 16) * 64, (bid / 16) * 64, cgt, cpb);
    } else if (bid < L2_CP + L2_XY) {
        int p = bid - L2_CP;
        part_xycy(smem, (p % 7) * 32, (p / 7) * 16, g_hxy, clsxy_w, clsxy_b[0], out);
    } else if (bid < L2_CP + L2_XY + L2_XC) {
        int p = bid - (L2_CP + L2_XY);
        part_xc(smem, (p % 14) * 8, (p / 14) * 32, xcw, xcb, out);
    } else {
        int p = bid - (L2_CP + L2_XY + L2_XC);
        // gate: wait until all 64 cproj tiles are published (all blocks
        // co-resident: 400 blocks < 8/SM * 148 slots, so no deadlock)
        if (threadIdx.x == 0) {
            while (atomicAdd(&g_cp_done, 0) < L2_CP) { }
        }
        __syncthreads();
        __threadfence();
        part_xycy(smem, (p % 7) * 32, (p / 7) * 16, g_cproj, clscy_w, clscy_b[0],
                  out + (size_t)BS * C);
    }
}

// ---------------- launch ----------------------------------------------------
extern "C" void kernel_launch(void* const* d_in, const int* in_sizes, int n_in,
                              void* d_out, int out_size) {
    (void)in_sizes; (void)n_in; (void)out_size;
    const float* x       = (const float*)d_in[0];
    const int*   c_gt    = (const int*)d_in[1];
    const float* y_emb   = (const float*)d_in[2];
    const float* c_emb   = (const float*)d_in[3];
    const float* xy_w    = (const float*)d_in[4];
    const float* xy_b    = (const float*)d_in[5];
    const float* xc_w1   = (const float*)d_in[6];
    const float* xc_b1   = (const float*)d_in[7];
    const float* clsxy_w = (const float*)d_in[8];
    const float* clsxy_b = (const float*)d_in[9];
    const float* clscy_w = (const float*)d_in[10];
    const float* clscy_b = (const float*)d_in[11];
    const float* xcw     = (const float*)d_in[12];
    const float* xcb     = (const float*)d_in[13];
    const float* cpw     = (const float*)d_in[14];
    const float* cpb     = (const float*)d_in[15];
    float* out = (float*)d_out;

    k_main<<<L1_GRID, 256>>>(x, y_emb, c_emb, xy_w, xy_b, xc_w1, xc_b1, cpw);
    k_mid<<<L2_GRID, 256>>>(c_gt, cpb, clsxy_w, clsxy_b, clscy_w, clscy_b,
                            xcw, xcb, out);
}

// round 14
// speedup vs baseline: 1.5171x; 1.5171x over previous
#include <cuda_runtime.h>
#include <cstdint>

#define BS 256
#define D  2048
#define H  1024
#define C  200
#define NC 112

// ---------------- scratch (static device allocations only) ----------------
__device__ float g_y1[C * H];
__device__ float g_c1[2 * NC * H];
__device__ float g_hxy[BS * H];
__device__ float g_hxc[BS * H];
__device__ float g_pn[NC * H];
__device__ float g_pd[NC * H];
__device__ float g_cproj[BS * H];

// ---------------- packed f32x2 helpers -------------------------------------
__device__ __forceinline__ uint64_t pack2(float x, float y) {
    uint64_t r;
    asm("mov.b64 %0, {%1, %2};" : "=l"(r) : "f"(x), "f"(y));
    return r;
}
__device__ __forceinline__ void fma2(uint64_t& d, uint64_t a, uint64_t b) {
    asm("fma.rn.f32x2 %0, %1, %2, %0;" : "+l"(d) : "l"(a), "l"(b));
}
__device__ __forceinline__ float2 unpack2(uint64_t v) {
    float2 f;
    asm("mov.b64 {%0, %1}, %2;" : "=f"(f.x), "=f"(f.y) : "l"(v));
    return f;
}

// ---------------- JAX threefry2x32 (partitionable semantics) --------------
__device__ __forceinline__ uint32_t rotl32(uint32_t v, int r) {
    return (v << r) | (v >> (32 - r));
}

__device__ __forceinline__ void tf2x32(uint32_t k0, uint32_t k1,
                                       uint32_t x0, uint32_t x1,
                                       uint32_t& o0, uint32_t& o1) {
    uint32_t ks2 = k0 ^ k1 ^ 0x1BD11BDAu;
    x0 += k0; x1 += k1;
#define TF_R(r) { x0 += x1; x1 = rotl32(x1, r); x1 ^= x0; }
    TF_R(13) TF_R(15) TF_R(26) TF_R(6)   x0 += k1;  x1 += ks2 + 1u;
    TF_R(17) TF_R(29) TF_R(16) TF_R(24)  x0 += ks2; x1 += k0 + 2u;
    TF_R(13) TF_R(15) TF_R(26) TF_R(6)   x0 += k0;  x1 += k1 + 3u;
    TF_R(17) TF_R(29) TF_R(16) TF_R(24)  x0 += k1;  x1 += ks2 + 4u;
    TF_R(13) TF_R(15) TF_R(26) TF_R(6)   x0 += ks2; x1 += k0 + 5u;
#undef TF_R
    o0 = x0; o1 = x1;
}

__device__ __forceinline__ bool drop_keep(uint32_t ka, uint32_t kb, uint32_t idx) {
    uint32_t a, b;
    tf2x32(ka, kb, 0u, idx, a, b);
    uint32_t bits = a ^ b;
    float u = __uint_as_float((bits >> 9) | 0x3F800000u) - 1.0f;
    return u < 0.8f;
}

// ---------------- shared-memory overlays ----------------------------------
struct SmemFc1  { float As[32][68]; float Bs[32][68]; };                   // 17408 B
struct SmemNorm { float red[256]; };
struct SmemCp   { float As[16][64]; float Bs[16][64]; float base[64]; };
struct SmemXY   { float Hs[64][17]; float Ys[64][33]; float ws[64]; };
struct SmemXC   { float Hs[32][33]; float Cs[32][17]; float Ws[32][9]; };

#define SMEM_BYTES 17408

// ---------------- part: 1 + l2norm of one row ------------------------------
__device__ void part_norm(char* smem, int r,
                          const float* __restrict__ ye,
                          const float* __restrict__ ce) {
    SmemNorm& s = *reinterpret_cast<SmemNorm*>(smem);
    const float* src;
    float* dst;
    if (r < C) { src = ye + (size_t)r * H;        dst = g_y1 + (size_t)r * H; }
    else       { src = ce + (size_t)(r - C) * H;  dst = g_c1 + (size_t)(r - C) * H; }
    int t = threadIdx.x;
    float4 v = *reinterpret_cast<const float4*>(&src[t * 4]);
    s.red[t] = v.x * v.x + v.y * v.y + v.z * v.z + v.w * v.w;
    __syncthreads();
    for (int o = 128; o; o >>= 1) {
        if (t < o) s.red[t] += s.red[t + o];
        __syncthreads();
    }
    float n = fmaxf(sqrtf(s.red[0]), 1e-12f);
    dst[t * 4 + 0] = 1.0f + v.x / n;
    dst[t * 4 + 1] = 1.0f + v.y / n;
    dst[t * 4 + 2] = 1.0f + v.z / n;
    dst[t * 4 + 3] = 1.0f + v.w / n;
}

// ---------------- part: fc1 GEMM (f32x2, 64x64 tile) + bias + dropout ------
__device__ void part_fc1(char* smem, int which, int n0, int m0,
                         const float* __restrict__ x,
                         const float* __restrict__ W,
                         const float* __restrict__ B,
                         float* __restrict__ out) {
    SmemFc1& s = *reinterpret_cast<SmemFc1*>(smem);
    const int tid = threadIdx.x;
    const int tx = tid % 16, ty = tid / 16;
    const int lr = tid / 4;
    const int lc = (tid % 4) * 8;
    uint64_t acc[4][2] = {};
    for (int k0 = 0; k0 < D; k0 += 32) {
        {
            const float* xr = &x[(size_t)(m0 + lr) * D + k0 + lc];
            float4 a0 = *reinterpret_cast<const float4*>(xr);
            float4 a1 = *reinterpret_cast<const float4*>(xr + 4);
            const float* wr = &W[(size_t)(n0 + lr) * D + k0 + lc];
            float4 b0 = *reinterpret_cast<const float4*>(wr);
            float4 b1 = *reinterpret_cast<const float4*>(wr + 4);
            s.As[lc + 0][lr] = a0.x; s.As[lc + 1][lr] = a0.y;
            s.As[lc + 2][lr] = a0.z; s.As[lc + 3][lr] = a0.w;
            s.As[lc + 4][lr] = a1.x; s.As[lc + 5][lr] = a1.y;
            s.As[lc + 6][lr] = a1.z; s.As[lc + 7][lr] = a1.w;
            s.Bs[lc + 0][lr] = b0.x; s.Bs[lc + 1][lr] = b0.y;
            s.Bs[lc + 2][lr] = b0.z; s.Bs[lc + 3][lr] = b0.w;
            s.Bs[lc + 4][lr] = b1.x; s.Bs[lc + 5][lr] = b1.y;
            s.Bs[lc + 6][lr] = b1.z; s.Bs[lc + 7][lr] = b1.w;
        }
        __syncthreads();
#pragma unroll
        for (int kk = 0; kk < 32; kk++) {
            float4 a = *reinterpret_cast<const float4*>(&s.As[kk][ty * 4]);
            float4 b = *reinterpret_cast<const float4*>(&s.Bs[kk][tx * 4]);
            uint64_t b01 = pack2(b.x, b.y);
            uint64_t b23 = pack2(b.z, b.w);
            uint64_t ap;
            ap = pack2(a.x, a.x); fma2(acc[0][0], ap, b01); fma2(acc[0][1], ap, b23);
            ap = pack2(a.y, a.y); fma2(acc[1][0], ap, b01); fma2(acc[1][1], ap, b23);
            ap = pack2(a.z, a.z); fma2(acc[2][0], ap, b01); fma2(acc[2][1], ap, b23);
            ap = pack2(a.w, a.w); fma2(acc[3][0], ap, b01); fma2(acc[3][1], ap, b23);
        }
        __syncthreads();
    }
    uint32_t ka, kb;
    tf2x32(0u, 42u, 0u, (uint32_t)which, ka, kb);
#pragma unroll
    for (int i = 0; i < 4; i++) {
        int b = m0 + ty * 4 + i;
#pragma unroll
        for (int jp = 0; jp < 2; jp++) {
            float2 v = unpack2(acc[i][jp]);
            int col = n0 + tx * 4 + jp * 2;
            float h0 = v.x + B[col];
            float h1 = v.y + B[col + 1];
            uint32_t i0 = (uint32_t)(b * H + col);
            out[(size_t)b * H + col]     = drop_keep(ka, kb, i0)      ? h0 / 0.8f : 0.0f;
            out[(size_t)b * H + col + 1] = drop_keep(ka, kb, i0 + 1u) ? h1 / 0.8f : 0.0f;
        }
    }
}

// ---------------- part: stream concept_proj_w once (register-resident e) ----
// block: one concept n, 64 rows. warp: 8 sequential rows, butterfly in 2
// batches of 4 (regs stay ~R9 level -> 2 blocks/SM). e-preamble amortized 2x.
__device__ void part_pnd(int n, int jg,
                         const float* __restrict__ ce,
                         const float* __restrict__ W) {
    const int tid = threadIdx.x;
    const int w = tid >> 5, lane = tid & 31;
    const int jbase = jg * 64 + w * 8;
    const size_t rs = (size_t)NC * H;
    float4 ep[8], en[8];
    {
        const float* epg = ce + (size_t)n * H + lane * 4;
        const float* eng = ce + (size_t)(NC + n) * H + lane * 4;
#pragma unroll
        for (int c = 0; c < 8; c++) {
            ep[c] = *reinterpret_cast<const float4*>(&epg[c * 128]);
            en[c] = *reinterpret_cast<const float4*>(&eng[c * 128]);
        }
    }
    const float* Wr = W + (size_t)jbase * rs + (size_t)n * H + lane * 4;
#pragma unroll 1
    for (int half = 0; half < 2; half++) {
        float ap[4], an[4];
#pragma unroll 1
        for (int r = 0; r < 4; r++) {
            const float* Wp = Wr + (size_t)(half * 4 + r) * rs;
            float4 wv[8];
#pragma unroll
            for (int c = 0; c < 8; c++)
                wv[c] = *reinterpret_cast<const float4*>(&Wp[c * 128]);
            float a = 0.f, b = 0.f;
#pragma unroll
            for (int c = 0; c < 8; c++) {
                a += wv[c].x * ep[c].x + wv[c].y * ep[c].y + wv[c].z * ep[c].z + wv[c].w * ep[c].w;
                b += wv[c].x * en[c].x + wv[c].y * en[c].y + wv[c].z * en[c].z + wv[c].w * en[c].w;
            }
            ap[r] = a; an[r] = b;
        }
#pragma unroll
        for (int off = 16; off; off >>= 1) {
#pragma unroll
            for (int r = 0; r < 4; r++) {
                ap[r] += __shfl_xor_sync(0xFFFFFFFFu, ap[r], off);
                an[r] += __shfl_xor_sync(0xFFFFFFFFu, an[r], off);
            }
        }
        if (lane == 0) {
#pragma unroll
            for (int r = 0; r < 4; r++) {
                int j = jbase + half * 4 + r;
                g_pn[n * H + j] = an[r];
                g_pd[n * H + j] = ap[r] - an[r];
            }
        }
    }
}

// ---------------- part: c_proj = (bias + sum_n pn) + gt @ pd ----------------
__device__ void part_cproj(char* smem, int j0, int m0,
                           const int* __restrict__ cgt,
                           const float* __restrict__ bias) {
    SmemCp& s = *reinterpret_cast<SmemCp*>(smem);
    const int tid = threadIdx.x;
    {
        int col = j0 + (tid & 63);
        if (tid < 64) s.base[tid] = bias[col];
        __syncthreads();
        int nb = (tid >> 6) * 28;
        float part = 0.f;
#pragma unroll 4
        for (int n = nb; n < nb + 28; n++) part += g_pn[n * H + col];
        atomicAdd(&s.base[tid & 63], part);
    }
    const int tx = tid % 16, ty = tid / 16;
    float acc[4][4] = {};
    for (int k0 = 0; k0 < NC; k0 += 16) {
        __syncthreads();
        {
            int r = tid / 4;
            int c = (tid % 4) * 4;
            int b = m0 + r;
#pragma unroll
            for (int q = 0; q < 4; q++)
                s.As[c + q][r] = (cgt[(size_t)b * NC + k0 + c + q] == 1) ? 1.0f : 0.0f;
        }
        {
            int kk = tid / 16;
            int j4 = (tid % 16) * 4;
            float4 v = *reinterpret_cast<const float4*>(&g_pd[(size_t)(k0 + kk) * H + j0 + j4]);
            *reinterpret_cast<float4*>(&s.Bs[kk][j4]) = v;
        }
        __syncthreads();
#pragma unroll
        for (int kk = 0; kk < 16; kk++) {
            float4 a = *reinterpret_cast<const float4*>(&s.As[kk][ty * 4]);
            float4 b = *reinterpret_cast<const float4*>(&s.Bs[kk][tx * 4]);
            float av[4] = {a.x, a.y, a.z, a.w};
            float bv[4] = {b.x, b.y, b.z, b.w};
#pragma unroll
            for (int i = 0; i < 4; i++)
#pragma unroll
                for (int j = 0; j < 4; j++)
                    acc[i][j] = fmaf(av[i], bv[j], acc[i][j]);
        }
    }
#pragma unroll
    for (int i = 0; i < 4; i++) {
        int b = m0 + ty * 4 + i;
#pragma unroll
        for (int j = 0; j < 4; j++) {
            int col = j0 + tx * 4 + j;
            g_cproj[(size_t)b * H + col] = acc[i][j] + s.base[tx * 4 + j];
        }
    }
}

// ---------------- part: xy / cy energy (32 c x 16 b tile, 64-k chunks) ------
__device__ void part_xycy(char* smem, int c0, int b0,
                          const float* __restrict__ A,
                          const float* __restrict__ clsw,
                          float bias,
                          float* __restrict__ out) {
    SmemXY& s = *reinterpret_cast<SmemXY*>(smem);
    const int tid = threadIdx.x;
    const int tx = tid % 16;
    const int ty = tid / 16;
    float acc0 = 0.f, acc1 = 0.f;
    for (int k0 = 0; k0 < H; k0 += 64) {
        {
            int row = tid / 16, ko = (tid % 16) * 4;
            float4 v = *reinterpret_cast<const float4*>(&A[(size_t)(b0 + row) * H + k0 + ko]);
            s.Hs[ko + 0][row] = v.x; s.Hs[ko + 1][row] = v.y;
            s.Hs[ko + 2][row] = v.z; s.Hs[ko + 3][row] = v.w;
        }
        {
            int lr = tid / 8, lc = (tid % 8) * 4;
            int cr = c0 + lr; if (cr > C - 1) cr = C - 1;
            const float* yr = &g_y1[(size_t)cr * H + k0];
            float4 u = *reinterpret_cast<const float4*>(&yr[lc]);
            s.Ys[lc + 0][lr] = u.x; s.Ys[lc + 1][lr] = u.y;
            s.Ys[lc + 2][lr] = u.z; s.Ys[lc + 3][lr] = u.w;
            float4 u2 = *reinterpret_cast<const float4*>(&yr[32 + lc]);
            s.Ys[32 + lc + 0][lr] = u2.x; s.Ys[32 + lc + 1][lr] = u2.y;
            s.Ys[32 + lc + 2][lr] = u2.z; s.Ys[32 + lc + 3][lr] = u2.w;
        }
        if (tid < 64) s.ws[tid] = clsw[k0 + tid];
        __syncthreads();
#pragma unroll
        for (int kk = 0; kk < 64; kk++) {
            float h = s.Hs[kk][ty];
            float y0 = s.Ys[kk][tx * 2 + 0];
            float y1 = s.Ys[kk][tx * 2 + 1];
            float w = s.ws[kk];
            acc0 = fmaf(fmaxf(h * y0, 0.f), w, acc0);
            acc1 = fmaf(fmaxf(h * y1, 0.f), w, acc1);
        }
        __syncthreads();
    }
    int b = b0 + ty;
    int c = c0 + tx * 2;
    if (c < C)     out[(size_t)b * C + c]     = acc0 + bias;
    if (c + 1 < C) out[(size_t)b * C + c + 1] = acc1 + bias;
}

// ---------------- part: xc energy -------------------------------------------
__device__ void part_xc(char* smem, int n0, int b0,
                        const float* __restrict__ xcw,
                        const float* __restrict__ xcb,
                        float* __restrict__ out) {
    SmemXC& s = *reinterpret_cast<SmemXC*>(smem);
    const int tid = threadIdx.x;
    const int tx = tid % 8;
    const int ty = tid / 8;
    const int lr = tid / 8;
    const int lc = (tid % 8) * 4;
    float acc0 = 0.f, acc1 = 0.f;
    for (int k0 = 0; k0 < H; k0 += 32) {
        {
            float4 v = *reinterpret_cast<const float4*>(&g_hxc[(size_t)(b0 + lr) * H + k0 + lc]);
            s.Hs[lc + 0][lr] = v.x; s.Hs[lc + 1][lr] = v.y;
            s.Hs[lc + 2][lr] = v.z; s.Hs[lc + 3][lr] = v.w;
        }
        {
            int loc = tid / 16;
            int kk = (tid % 16) * 2;
            int nl = loc >> 1, sx = loc & 1;
            int row = sx * NC + (n0 + nl);
            float2 v = *reinterpret_cast<const float2*>(&g_c1[(size_t)row * H + k0 + kk]);
            s.Cs[kk + 0][nl * 2 + sx] = v.x;
            s.Cs[kk + 1][nl * 2 + sx] = v.y;
        }
        {
            int nl = tid / 32;
            int kk = tid % 32;
            s.Ws[kk][nl] = xcw[(size_t)(n0 + nl) * H + k0 + kk];
        }
        __syncthreads();
#pragma unroll
        for (int kk = 0; kk < 32; kk++) {
            float h = s.Hs[kk][ty];
            float w = s.Ws[kk][tx];
            float cp = s.Cs[kk][tx * 2 + 0];
            float cn = s.Cs[kk][tx * 2 + 1];
            acc0 = fmaf(fmaxf(h * cp, 0.f), w, acc0);
            acc1 = fmaf(fmaxf(h * cn, 0.f), w, acc1);
        }
        __syncthreads();
    }
    int b = b0 + ty, n = n0 + tx;
    float bb = xcb[n];
    size_t base = (size_t)(2 * BS * C) + (size_t)b * (NC * 2) + n * 2;
    out[base + 0] = acc0 + bb;
    out[base + 1] = acc1 + bb;
}

// ================= launch 1: fc1 + norm + pnd (overlapped) ==================
#define L1_FC1   128
#define L1_NORM  (C + 2 * NC)                 // 424
#define L1_PND   (NC * 16)                    // 1792 (64-j groups)
#define L1_GRID  (L1_FC1 + L1_NORM + L1_PND)

__global__ __launch_bounds__(256, 2) void k_main(const float* __restrict__ x,
                                                 const float* __restrict__ ye,
                                                 const float* __restrict__ ce,
                                                 const float* __restrict__ w0,
                                                 const float* __restrict__ b0,
                                                 const float* __restrict__ w1,
                                                 const float* __restrict__ b1,
                                                 const float* __restrict__ cpw) {
    __shared__ __align__(16) char smem[SMEM_BYTES];
    int bid = blockIdx.x;
    if (bid < L1_FC1) {
        int which = bid >> 6;
        int rem = bid & 63;
        part_fc1(smem, which, (rem % 16) * 64, (rem / 16) * 64, x,
                 which ? w1 : w0, which ? b1 : b0, which ? g_hxc : g_hxy);
    } else if (bid < L1_FC1 + L1_NORM) {
        part_norm(smem, bid - L1_FC1, ye, ce);
    } else {
        int p = bid - (L1_FC1 + L1_NORM);
        part_pnd(p % NC, p / NC, ce, cpw);
    }
}

// ================= launch 2: cproj + xy-energy + xc-energy ==================
#define L2_CP   (16 * 4)              // 64
#define L2_XY   (7 * 16)              // 112
#define L2_XC   (14 * 8)              // 112
#define L2_GRID (L2_CP + L2_XY + L2_XC)

__global__ __launch_bounds__(256) void k_mid(const int* __restrict__ cgt,
                                             const float* __restrict__ cpb,
                                             const float* __restrict__ clsxy_w,
                                             const float* __restrict__ clsxy_b,
                                             const float* __restrict__ xcw,
                                             const float* __restrict__ xcb,
                                             float* __restrict__ out) {
    __shared__ __align__(16) char smem[SMEM_BYTES];
    int bid = blockIdx.x;
    if (bid < L2_CP) {
        part_cproj(smem, (bid % 16) * 64, (bid / 16) * 64, cgt, cpb);
    } else if (bid < L2_CP + L2_XY) {
        int p = bid - L2_CP;
        part_xycy(smem, (p % 7) * 32, (p / 7) * 16, g_hxy, clsxy_w, clsxy_b[0], out);
    } else {
        int p = bid - (L2_CP + L2_XY);
        part_xc(smem, (p % 14) * 8, (p / 14) * 32, xcw, xcb, out);
    }
}

// ================= launch 3: cy-energy ======================================
__global__ __launch_bounds__(256) void k_cy(const float* __restrict__ clscy_w,
                                            const float* __restrict__ clscy_b,
                                            float* __restrict__ out) {
    __shared__ __align__(16) char smem[SMEM_BYTES];
    int bid = blockIdx.x;
    part_xycy(smem, (bid % 7) * 32, (bid / 7) * 16, g_cproj, clscy_w, clscy_b[0],
              out + (size_t)BS * C);
}

// ---------------- launch ----------------------------------------------------
extern "C" void kernel_launch(void* const* d_in, const int* in_sizes, int n_in,
                              void* d_out, int out_size) {
    (void)in_sizes; (void)n_in; (void)out_size;
    const float* x       = (const float*)d_in[0];
    const int*   c_gt    = (const int*)d_in[1];
    const float* y_emb   = (const float*)d_in[2];
    const float* c_emb   = (const float*)d_in[3];
    const float* xy_w    = (const float*)d_in[4];
    const float* xy_b    = (const float*)d_in[5];
    const float* xc_w1   = (const float*)d_in[6];
    const float* xc_b1   = (const float*)d_in[7];
    const float* clsxy_w = (const float*)d_in[8];
    const float* clsxy_b = (const float*)d_in[9];
    const float* clscy_w = (const float*)d_in[10];
    const float* clscy_b = (const float*)d_in[11];
    const float* xcw     = (const float*)d_in[12];
    const float* xcb     = (const float*)d_in[13];
    const float* cpw     = (const float*)d_in[14];
    const float* cpb     = (const float*)d_in[15];
    float* out = (float*)d_out;

    k_main<<<L1_GRID, 256>>>(x, y_emb, c_emb, xy_w, xy_b, xc_w1, xc_b1, cpw);
    k_mid<<<L2_GRID, 256>>>(c_gt, cpb, clsxy_w, clsxy_b, xcw, xcb, out);
    k_cy<<<7 * 16, 256>>>(clscy_w, clscy_b, out);
}

// round 15
// speedup vs baseline: 1.5566x; 1.0260x over previous
#include <cuda_runtime.h>
#include <cstdint>

#define BS 256
#define D  2048
#define H  1024
#define C  200
#define NC 112

// ---------------- scratch (static device allocations only) ----------------
__device__ float g_y1[C * H];
__device__ float g_c1[2 * NC * H];
__device__ float g_hxy[BS * H];
__device__ float g_hxc[BS * H];
__device__ float g_pn[NC * H];
__device__ float g_pd[NC * H];
__device__ float g_cproj[BS * H];
__device__ float g_pxy[2 * BS * C];        // xy k-split partials
__device__ float g_pxc[2 * BS * NC * 2];   // xc k-split partials

// ---------------- packed f32x2 helpers -------------------------------------
__device__ __forceinline__ uint64_t pack2(float x, float y) {
    uint64_t r;
    asm("mov.b64 %0, {%1, %2};" : "=l"(r) : "f"(x), "f"(y));
    return r;
}
__device__ __forceinline__ void fma2(uint64_t& d, uint64_t a, uint64_t b) {
    asm("fma.rn.f32x2 %0, %1, %2, %0;" : "+l"(d) : "l"(a), "l"(b));
}
__device__ __forceinline__ float2 unpack2(uint64_t v) {
    float2 f;
    asm("mov.b64 {%0, %1}, %2;" : "=f"(f.x), "=f"(f.y) : "l"(v));
    return f;
}

// ---------------- JAX threefry2x32 (partitionable semantics) --------------
__device__ __forceinline__ uint32_t rotl32(uint32_t v, int r) {
    return (v << r) | (v >> (32 - r));
}

__device__ __forceinline__ void tf2x32(uint32_t k0, uint32_t k1,
                                       uint32_t x0, uint32_t x1,
                                       uint32_t& o0, uint32_t& o1) {
    uint32_t ks2 = k0 ^ k1 ^ 0x1BD11BDAu;
    x0 += k0; x1 += k1;
#define TF_R(r) { x0 += x1; x1 = rotl32(x1, r); x1 ^= x0; }
    TF_R(13) TF_R(15) TF_R(26) TF_R(6)   x0 += k1;  x1 += ks2 + 1u;
    TF_R(17) TF_R(29) TF_R(16) TF_R(24)  x0 += ks2; x1 += k0 + 2u;
    TF_R(13) TF_R(15) TF_R(26) TF_R(6)   x0 += k0;  x1 += k1 + 3u;
    TF_R(17) TF_R(29) TF_R(16) TF_R(24)  x0 += k1;  x1 += ks2 + 4u;
    TF_R(13) TF_R(15) TF_R(26) TF_R(6)   x0 += ks2; x1 += k0 + 5u;
#undef TF_R
    o0 = x0; o1 = x1;
}

__device__ __forceinline__ bool drop_keep(uint32_t ka, uint32_t kb, uint32_t idx) {
    uint32_t a, b;
    tf2x32(ka, kb, 0u, idx, a, b);
    uint32_t bits = a ^ b;
    float u = __uint_as_float((bits >> 9) | 0x3F800000u) - 1.0f;
    return u < 0.8f;
}

// ---------------- shared-memory overlays ----------------------------------
struct SmemFc1  { float As[32][68]; float Bs[32][68]; };                   // 17408 B
struct SmemNorm { float red[256]; };
struct SmemCp   { float As[16][64]; float Bs[16][64]; float base[64]; };
struct SmemXY   { float Hs[64][17]; float Ys[64][33]; float ws[64]; };
struct SmemXC   { float Hs[32][33]; float Cs[32][17]; float Ws[32][9]; };

#define SMEM_BYTES 17408

// ---------------- part: 1 + l2norm of one row ------------------------------
__device__ void part_norm(char* smem, int r,
                          const float* __restrict__ ye,
                          const float* __restrict__ ce) {
    SmemNorm& s = *reinterpret_cast<SmemNorm*>(smem);
    const float* src;
    float* dst;
    if (r < C) { src = ye + (size_t)r * H;        dst = g_y1 + (size_t)r * H; }
    else       { src = ce + (size_t)(r - C) * H;  dst = g_c1 + (size_t)(r - C) * H; }
    int t = threadIdx.x;
    float4 v = *reinterpret_cast<const float4*>(&src[t * 4]);
    s.red[t] = v.x * v.x + v.y * v.y + v.z * v.z + v.w * v.w;
    __syncthreads();
    for (int o = 128; o; o >>= 1) {
        if (t < o) s.red[t] += s.red[t + o];
        __syncthreads();
    }
    float n = fmaxf(sqrtf(s.red[0]), 1e-12f);
    dst[t * 4 + 0] = 1.0f + v.x / n;
    dst[t * 4 + 1] = 1.0f + v.y / n;
    dst[t * 4 + 2] = 1.0f + v.z / n;
    dst[t * 4 + 3] = 1.0f + v.w / n;
}

// ---------------- part: fc1 GEMM (f32x2, 64x64 tile) + bias + dropout ------
__device__ void part_fc1(char* smem, int which, int n0, int m0,
                         const float* __restrict__ x,
                         const float* __restrict__ W,
                         const float* __restrict__ B,
                         float* __restrict__ out) {
    SmemFc1& s = *reinterpret_cast<SmemFc1*>(smem);
    const int tid = threadIdx.x;
    const int tx = tid % 16, ty = tid / 16;
    const int lr = tid / 4;
    const int lc = (tid % 4) * 8;
    uint64_t acc[4][2] = {};
    for (int k0 = 0; k0 < D; k0 += 32) {
        {
            const float* xr = &x[(size_t)(m0 + lr) * D + k0 + lc];
            float4 a0 = *reinterpret_cast<const float4*>(xr);
            float4 a1 = *reinterpret_cast<const float4*>(xr + 4);
            const float* wr = &W[(size_t)(n0 + lr) * D + k0 + lc];
            float4 b0 = *reinterpret_cast<const float4*>(wr);
            float4 b1 = *reinterpret_cast<const float4*>(wr + 4);
            s.As[lc + 0][lr] = a0.x; s.As[lc + 1][lr] = a0.y;
            s.As[lc + 2][lr] = a0.z; s.As[lc + 3][lr] = a0.w;
            s.As[lc + 4][lr] = a1.x; s.As[lc + 5][lr] = a1.y;
            s.As[lc + 6][lr] = a1.z; s.As[lc + 7][lr] = a1.w;
            s.Bs[lc + 0][lr] = b0.x; s.Bs[lc + 1][lr] = b0.y;
            s.Bs[lc + 2][lr] = b0.z; s.Bs[lc + 3][lr] = b0.w;
            s.Bs[lc + 4][lr] = b1.x; s.Bs[lc + 5][lr] = b1.y;
            s.Bs[lc + 6][lr] = b1.z; s.Bs[lc + 7][lr] = b1.w;
        }
        __syncthreads();
#pragma unroll
        for (int kk = 0; kk < 32; kk++) {
            float4 a = *reinterpret_cast<const float4*>(&s.As[kk][ty * 4]);
            float4 b = *reinterpret_cast<const float4*>(&s.Bs[kk][tx * 4]);
            uint64_t b01 = pack2(b.x, b.y);
            uint64_t b23 = pack2(b.z, b.w);
            uint64_t ap;
            ap = pack2(a.x, a.x); fma2(acc[0][0], ap, b01); fma2(acc[0][1], ap, b23);
            ap = pack2(a.y, a.y); fma2(acc[1][0], ap, b01); fma2(acc[1][1], ap, b23);
            ap = pack2(a.z, a.z); fma2(acc[2][0], ap, b01); fma2(acc[2][1], ap, b23);
            ap = pack2(a.w, a.w); fma2(acc[3][0], ap, b01); fma2(acc[3][1], ap, b23);
        }
        __syncthreads();
    }
    uint32_t ka, kb;
    tf2x32(0u, 42u, 0u, (uint32_t)which, ka, kb);
#pragma unroll
    for (int i = 0; i < 4; i++) {
        int b = m0 + ty * 4 + i;
#pragma unroll
        for (int jp = 0; jp < 2; jp++) {
            float2 v = unpack2(acc[i][jp]);
            int col = n0 + tx * 4 + jp * 2;
            float h0 = v.x + B[col];
            float h1 = v.y + B[col + 1];
            uint32_t i0 = (uint32_t)(b * H + col);
            out[(size_t)b * H + col]     = drop_keep(ka, kb, i0)      ? h0 / 0.8f : 0.0f;
            out[(size_t)b * H + col + 1] = drop_keep(ka, kb, i0 + 1u) ? h1 / 0.8f : 0.0f;
        }
    }
}

// ---------------- part: stream concept_proj_w once (register-resident e) ----
__device__ void part_pnd(int n, int jg,
                         const float* __restrict__ ce,
                         const float* __restrict__ W) {
    const int tid = threadIdx.x;
    const int w = tid >> 5, lane = tid & 31;
    const int jbase = jg * 64 + w * 8;
    const size_t rs = (size_t)NC * H;
    float4 ep[8], en[8];
    {
        const float* epg = ce + (size_t)n * H + lane * 4;
        const float* eng = ce + (size_t)(NC + n) * H + lane * 4;
#pragma unroll
        for (int c = 0; c < 8; c++) {
            ep[c] = *reinterpret_cast<const float4*>(&epg[c * 128]);
            en[c] = *reinterpret_cast<const float4*>(&eng[c * 128]);
        }
    }
    const float* Wr = W + (size_t)jbase * rs + (size_t)n * H + lane * 4;
#pragma unroll 1
    for (int half = 0; half < 2; half++) {
        float ap[4], an[4];
#pragma unroll 1
        for (int r = 0; r < 4; r++) {
            const float* Wp = Wr + (size_t)(half * 4 + r) * rs;
            float4 wv[8];
#pragma unroll
            for (int c = 0; c < 8; c++)
                wv[c] = *reinterpret_cast<const float4*>(&Wp[c * 128]);
            float a = 0.f, b = 0.f;
#pragma unroll
            for (int c = 0; c < 8; c++) {
                a += wv[c].x * ep[c].x + wv[c].y * ep[c].y + wv[c].z * ep[c].z + wv[c].w * ep[c].w;
                b += wv[c].x * en[c].x + wv[c].y * en[c].y + wv[c].z * en[c].z + wv[c].w * en[c].w;
            }
            ap[r] = a; an[r] = b;
        }
#pragma unroll
        for (int off = 16; off; off >>= 1) {
#pragma unroll
            for (int r = 0; r < 4; r++) {
                ap[r] += __shfl_xor_sync(0xFFFFFFFFu, ap[r], off);
                an[r] += __shfl_xor_sync(0xFFFFFFFFu, an[r], off);
            }
        }
        if (lane == 0) {
#pragma unroll
            for (int r = 0; r < 4; r++) {
                int j = jbase + half * 4 + r;
                g_pn[n * H + j] = an[r];
                g_pd[n * H + j] = ap[r] - an[r];
            }
        }
    }
}

// ---------------- part: c_proj = (bias + sum_n pn) + gt @ pd ----------------
__device__ void part_cproj(char* smem, int j0, int m0,
                           const int* __restrict__ cgt,
                           const float* __restrict__ bias) {
    SmemCp& s = *reinterpret_cast<SmemCp*>(smem);
    const int tid = threadIdx.x;
    {
        int col = j0 + (tid & 63);
        if (tid < 64) s.base[tid] = bias[col];
        __syncthreads();
        int nb = (tid >> 6) * 28;
        float part = 0.f;
#pragma unroll 4
        for (int n = nb; n < nb + 28; n++) part += g_pn[n * H + col];
        atomicAdd(&s.base[tid & 63], part);
    }
    const int tx = tid % 16, ty = tid / 16;
    float acc[4][4] = {};
    for (int k0 = 0; k0 < NC; k0 += 16) {
        __syncthreads();
        {
            int r = tid / 4;
            int c = (tid % 4) * 4;
            int b = m0 + r;
#pragma unroll
            for (int q = 0; q < 4; q++)
                s.As[c + q][r] = (cgt[(size_t)b * NC + k0 + c + q] == 1) ? 1.0f : 0.0f;
        }
        {
            int kk = tid / 16;
            int j4 = (tid % 16) * 4;
            float4 v = *reinterpret_cast<const float4*>(&g_pd[(size_t)(k0 + kk) * H + j0 + j4]);
            *reinterpret_cast<float4*>(&s.Bs[kk][j4]) = v;
        }
        __syncthreads();
#pragma unroll
        for (int kk = 0; kk < 16; kk++) {
            float4 a = *reinterpret_cast<const float4*>(&s.As[kk][ty * 4]);
            float4 b = *reinterpret_cast<const float4*>(&s.Bs[kk][tx * 4]);
            float av[4] = {a.x, a.y, a.z, a.w};
            float bv[4] = {b.x, b.y, b.z, b.w};
#pragma unroll
            for (int i = 0; i < 4; i++)
#pragma unroll
                for (int j = 0; j < 4; j++)
                    acc[i][j] = fmaf(av[i], bv[j], acc[i][j]);
        }
    }
#pragma unroll
    for (int i = 0; i < 4; i++) {
        int b = m0 + ty * 4 + i;
#pragma unroll
        for (int j = 0; j < 4; j++) {
            int col = j0 + tx * 4 + j;
            g_cproj[(size_t)b * H + col] = acc[i][j] + s.base[tx * 4 + j];
        }
    }
}

// ---------------- part: xy / cy energy over k range [kbeg,kend) -------------
// dst[b*C + c] = sum + bias   (32 c x 16 b tile, 64-k chunks)
__device__ void part_xycy(char* smem, int c0, int b0,
                          const float* __restrict__ A,
                          const float* __restrict__ clsw,
                          float bias, int kbeg, int kend,
                          float* __restrict__ dst) {
    SmemXY& s = *reinterpret_cast<SmemXY*>(smem);
    const int tid = threadIdx.x;
    const int tx = tid % 16;
    const int ty = tid / 16;
    float acc0 = 0.f, acc1 = 0.f;
    for (int k0 = kbeg; k0 < kend; k0 += 64) {
        {
            int row = tid / 16, ko = (tid % 16) * 4;
            float4 v = *reinterpret_cast<const float4*>(&A[(size_t)(b0 + row) * H + k0 + ko]);
            s.Hs[ko + 0][row] = v.x; s.Hs[ko + 1][row] = v.y;
            s.Hs[ko + 2][row] = v.z; s.Hs[ko + 3][row] = v.w;
        }
        {
            int lr = tid / 8, lc = (tid % 8) * 4;
            int cr = c0 + lr; if (cr > C - 1) cr = C - 1;
            const float* yr = &g_y1[(size_t)cr * H + k0];
            float4 u = *reinterpret_cast<const float4*>(&yr[lc]);
            s.Ys[lc + 0][lr] = u.x; s.Ys[lc + 1][lr] = u.y;
            s.Ys[lc + 2][lr] = u.z; s.Ys[lc + 3][lr] = u.w;
            float4 u2 = *reinterpret_cast<const float4*>(&yr[32 + lc]);
            s.Ys[32 + lc + 0][lr] = u2.x; s.Ys[32 + lc + 1][lr] = u2.y;
            s.Ys[32 + lc + 2][lr] = u2.z; s.Ys[32 + lc + 3][lr] = u2.w;
        }
        if (tid < 64) s.ws[tid] = clsw[k0 + tid];
        __syncthreads();
#pragma unroll
        for (int kk = 0; kk < 64; kk++) {
            float h = s.Hs[kk][ty];
            float y0 = s.Ys[kk][tx * 2 + 0];
            float y1 = s.Ys[kk][tx * 2 + 1];
            float w = s.ws[kk];
            acc0 = fmaf(fmaxf(h * y0, 0.f), w, acc0);
            acc1 = fmaf(fmaxf(h * y1, 0.f), w, acc1);
        }
        __syncthreads();
    }
    int b = b0 + ty;
    int c = c0 + tx * 2;
    if (c < C)     dst[(size_t)b * C + c]     = acc0 + bias;
    if (c + 1 < C) dst[(size_t)b * C + c + 1] = acc1 + bias;
}

// ---------------- part: xc energy over k range [kbeg,kend) ------------------
// dst[b*(2NC) + n*2 + s] = sum (+xcb[n] if xcb != nullptr)
__device__ void part_xc(char* smem, int n0, int b0,
                        const float* __restrict__ xcw,
                        const float* __restrict__ xcb,
                        int kbeg, int kend,
                        float* __restrict__ dst) {
    SmemXC& s = *reinterpret_cast<SmemXC*>(smem);
    const int tid = threadIdx.x;
    const int tx = tid % 8;
    const int ty = tid / 8;
    const int lr = tid / 8;
    const int lc = (tid % 8) * 4;
    float acc0 = 0.f, acc1 = 0.f;
    for (int k0 = kbeg; k0 < kend; k0 += 32) {
        {
            float4 v = *reinterpret_cast<const float4*>(&g_hxc[(size_t)(b0 + lr) * H + k0 + lc]);
            s.Hs[lc + 0][lr] = v.x; s.Hs[lc + 1][lr] = v.y;
            s.Hs[lc + 2][lr] = v.z; s.Hs[lc + 3][lr] = v.w;
        }
        {
            int loc = tid / 16;
            int kk = (tid % 16) * 2;
            int nl = loc >> 1, sx = loc & 1;
            int row = sx * NC + (n0 + nl);
            float2 v = *reinterpret_cast<const float2*>(&g_c1[(size_t)row * H + k0 + kk]);
            s.Cs[kk + 0][nl * 2 + sx] = v.x;
            s.Cs[kk + 1][nl * 2 + sx] = v.y;
        }
        {
            int nl = tid / 32;
            int kk = tid % 32;
            s.Ws[kk][nl] = xcw[(size_t)(n0 + nl) * H + k0 + kk];
        }
        __syncthreads();
#pragma unroll
        for (int kk = 0; kk < 32; kk++) {
            float h = s.Hs[kk][ty];
            float w = s.Ws[kk][tx];
            float cp = s.Cs[kk][tx * 2 + 0];
            float cn = s.Cs[kk][tx * 2 + 1];
            acc0 = fmaf(fmaxf(h * cp, 0.f), w, acc0);
            acc1 = fmaf(fmaxf(h * cn, 0.f), w, acc1);
        }
        __syncthreads();
    }
    int b = b0 + ty, n = n0 + tx;
    float bb = xcb ? xcb[n] : 0.0f;
    size_t base = (size_t)b * (NC * 2) + n * 2;
    dst[base + 0] = acc0 + bb;
    dst[base + 1] = acc1 + bb;
}

// ================= launch 1: fc1 + norm + pnd (overlapped) ==================
#define L1_FC1   128
#define L1_NORM  (C + 2 * NC)                 // 424
#define L1_PND   (NC * 16)                    // 1792 (64-j groups)
#define L1_GRID  (L1_FC1 + L1_NORM + L1_PND)

__global__ __launch_bounds__(256, 2) void k_main(const float* __restrict__ x,
                                                 const float* __restrict__ ye,
                                                 const float* __restrict__ ce,
                                                 const float* __restrict__ w0,
                                                 const float* __restrict__ b0,
                                                 const float* __restrict__ w1,
                                                 const float* __restrict__ b1,
                                                 const float* __restrict__ cpw) {
    __shared__ __align__(16) char smem[SMEM_BYTES];
    int bid = blockIdx.x;
    if (bid < L1_FC1) {
        int which = bid >> 6;
        int rem = bid & 63;
        part_fc1(smem, which, (rem % 16) * 64, (rem / 16) * 64, x,
                 which ? w1 : w0, which ? b1 : b0, which ? g_hxc : g_hxy);
    } else if (bid < L1_FC1 + L1_NORM) {
        part_norm(smem, bid - L1_FC1, ye, ce);
    } else {
        int p = bid - (L1_FC1 + L1_NORM);
        part_pnd(p % NC, p / NC, ce, cpw);
    }
}

// ====== launch 2: cproj + xy (k-split 2) + xc (k-split 2) ===================
#define L2_CP   (16 * 4)              // 64
#define L2_XY   (2 * 112)             // 224 (2 k-slices x 7x16 tiles)
#define L2_XC   (2 * 112)             // 224 (2 k-slices x 14x8 tiles)
#define L2_GRID (L2_CP + L2_XY + L2_XC)   // 512

__global__ __launch_bounds__(256) void k_mid(const int* __restrict__ cgt,
                                             const float* __restrict__ cpb,
                                             const float* __restrict__ clsxy_w,
                                             const float* __restrict__ xcw,
                                             float* __restrict__ out) {
    (void)out;
    __shared__ __align__(16) char smem[SMEM_BYTES];
    int bid = blockIdx.x;
    if (bid < L2_CP) {
        part_cproj(smem, (bid % 16) * 64, (bid / 16) * 64, cgt, cpb);
    } else if (bid < L2_CP + L2_XY) {
        int p = bid - L2_CP;
        int sl = p / 112, t = p % 112;
        part_xycy(smem, (t % 7) * 32, (t / 7) * 16, g_hxy, clsxy_w, 0.0f,
                  sl * 512, sl * 512 + 512, g_pxy + (size_t)sl * BS * C);
    } else {
        int p = bid - (L2_CP + L2_XY);
        int sl = p / 112, t = p % 112;
        part_xc(smem, (t % 14) * 8, (t / 14) * 32, xcw, nullptr,
                sl * 512, sl * 512 + 512, g_pxc + (size_t)sl * BS * NC * 2);
    }
}

// ====== launch 3: cy-energy + combine partials ==============================
#define L3_CY   112
#define L3_XYC  (BS * C / 1024)           // 50
#define L3_XCC  (BS * NC * 2 / 1024)      // 56
#define L3_GRID (L3_CY + L3_XYC + L3_XCC) // 218

__global__ __launch_bounds__(256) void k_fin(const float* __restrict__ clscy_w,
                                             const float* __restrict__ clscy_b,
                                             const float* __restrict__ clsxy_b,
                                             const float* __restrict__ xcb,
                                             float* __restrict__ out) {
    __shared__ __align__(16) char smem[SMEM_BYTES];
    int bid = blockIdx.x;
    if (bid < L3_CY) {
        part_xycy(smem, (bid % 7) * 32, (bid / 7) * 16, g_cproj, clscy_w,
                  clscy_b[0], 0, H, out + (size_t)BS * C);
    } else if (bid < L3_CY + L3_XYC) {
        int i = (bid - L3_CY) * 1024 + threadIdx.x * 4;
        float bias = clsxy_b[0];
        float4 a = *reinterpret_cast<const float4*>(&g_pxy[i]);
        float4 b = *reinterpret_cast<const float4*>(&g_pxy[BS * C + i]);
        float4 r = make_float4(a.x + b.x + bias, a.y + b.y + bias,
                               a.z + b.z + bias, a.w + b.w + bias);
        *reinterpret_cast<float4*>(&out[i]) = r;
    } else {
        int i = (bid - L3_CY - L3_XYC) * 1024 + threadIdx.x * 4;
        float4 a = *reinterpret_cast<const float4*>(&g_pxc[i]);
        float4 b = *reinterpret_cast<const float4*>(&g_pxc[BS * NC * 2 + i]);
        // element e at flat index i+e: n = ((i+e) % (2*NC)) / 2
        float r[4] = {a.x + b.x, a.y + b.y, a.z + b.z, a.w + b.w};
#pragma unroll
        for (int e = 0; e < 4; e++) {
            int n = ((i + e) % (2 * NC)) >> 1;
            r[e] += xcb[n];
        }
        float* o = out + (size_t)2 * BS * C + i;
        o[0] = r[0]; o[1] = r[1]; o[2] = r[2]; o[3] = r[3];
    }
}

// ---------------- launch ----------------------------------------------------
extern "C" void kernel_launch(void* const* d_in, const int* in_sizes, int n_in,
                              void* d_out, int out_size) {
    (void)in_sizes; (void)n_in; (void)out_size;
    const float* x       = (const float*)d_in[0];
    const int*   c_gt    = (const int*)d_in[1];
    const float* y_emb   = (const float*)d_in[2];
    const float* c_emb   = (const float*)d_in[3];
    const float* xy_w    = (const float*)d_in[4];
    const float* xy_b    = (const float*)d_in[5];
    const float* xc_w1   = (const float*)d_in[6];
    const float* xc_b1   = (const float*)d_in[7];
    const float* clsxy_w = (const float*)d_in[8];
    const float* clsxy_b = (const float*)d_in[9];
    const float* clscy_w = (const float*)d_in[10];
    const float* clscy_b = (const float*)d_in[11];
    const float* xcw     = (const float*)d_in[12];
    const float* xcb     = (const float*)d_in[13];
    const float* cpw     = (const float*)d_in[14];
    const float* cpb     = (const float*)d_in[15];
    float* out = (float*)d_out;

    k_main<<<L1_GRID, 256>>>(x, y_emb, c_emb, xy_w, xy_b, xc_w1, xc_b1, cpw);
    k_mid<<<L2_GRID, 256>>>(c_gt, cpb, clsxy_w, xcw, out);
    k_fin<<<L3_GRID, 256>>>(clscy_w, clscy_b, clsxy_b, xcb, out);
}

// round 16
// speedup vs baseline: 1.6095x; 1.0340x over previous
#include <cuda_runtime.h>
#include <cstdint>

#define BS 256
#define D  2048
#define H  1024
#define C  200
#define NC 112

// ---------------- scratch (static device allocations only) ----------------
__device__ float g_y1[C * H];
__device__ float g_c1[2 * NC * H];
__device__ float g_hxy[BS * H];
__device__ float g_hxc[BS * H];
__device__ float g_pn[NC * H];
__device__ float g_pd[NC * H];
__device__ float g_cproj[BS * H];
__device__ int   g_cnt_cp;

// ---------------- packed f32x2 helpers -------------------------------------
__device__ __forceinline__ uint64_t pack2(float x, float y) {
    uint64_t r;
    asm("mov.b64 %0, {%1, %2};" : "=l"(r) : "f"(x), "f"(y));
    return r;
}
__device__ __forceinline__ void fma2(uint64_t& d, uint64_t a, uint64_t b) {
    asm("fma.rn.f32x2 %0, %1, %2, %0;" : "+l"(d) : "l"(a), "l"(b));
}
__device__ __forceinline__ float2 unpack2(uint64_t v) {
    float2 f;
    asm("mov.b64 {%0, %1}, %2;" : "=f"(f.x), "=f"(f.y) : "l"(v));
    return f;
}

// ---------------- JAX threefry2x32 (partitionable semantics) --------------
__device__ __forceinline__ uint32_t rotl32(uint32_t v, int r) {
    return (v << r) | (v >> (32 - r));
}

__device__ __forceinline__ void tf2x32(uint32_t k0, uint32_t k1,
                                       uint32_t x0, uint32_t x1,
                                       uint32_t& o0, uint32_t& o1) {
    uint32_t ks2 = k0 ^ k1 ^ 0x1BD11BDAu;
    x0 += k0; x1 += k1;
#define TF_R(r) { x0 += x1; x1 = rotl32(x1, r); x1 ^= x0; }
    TF_R(13) TF_R(15) TF_R(26) TF_R(6)   x0 += k1;  x1 += ks2 + 1u;
    TF_R(17) TF_R(29) TF_R(16) TF_R(24)  x0 += ks2; x1 += k0 + 2u;
    TF_R(13) TF_R(15) TF_R(26) TF_R(6)   x0 += k0;  x1 += k1 + 3u;
    TF_R(17) TF_R(29) TF_R(16) TF_R(24)  x0 += k1;  x1 += ks2 + 4u;
    TF_R(13) TF_R(15) TF_R(26) TF_R(6)   x0 += ks2; x1 += k0 + 5u;
#undef TF_R
    o0 = x0; o1 = x1;
}

__device__ __forceinline__ bool drop_keep(uint32_t ka, uint32_t kb, uint32_t idx) {
    uint32_t a, b;
    tf2x32(ka, kb, 0u, idx, a, b);
    uint32_t bits = a ^ b;
    float u = __uint_as_float((bits >> 9) | 0x3F800000u) - 1.0f;
    return u < 0.8f;
}

// ---------------- shared-memory overlays ----------------------------------
struct SmemFc1  { float As[32][68]; float Bs[32][68]; };                   // 17408 B
struct SmemNorm { float red[256]; };
struct SmemCp   { float As[16][64]; float Bs[16][64]; float base[64]; };
struct SmemXY   { float Hs[64][17]; float Ys[64][33]; float ws[64]; };
struct SmemXC   { float Hs[32][33]; float Cs[32][17]; float Ws[32][9]; };

#define SMEM_BYTES 17408

// ---------------- part: 1 + l2norm of one row ------------------------------
__device__ void part_norm(char* smem, int r,
                          const float* __restrict__ ye,
                          const float* __restrict__ ce) {
    SmemNorm& s = *reinterpret_cast<SmemNorm*>(smem);
    const float* src;
    float* dst;
    if (r < C) { src = ye + (size_t)r * H;        dst = g_y1 + (size_t)r * H; }
    else       { src = ce + (size_t)(r - C) * H;  dst = g_c1 + (size_t)(r - C) * H; }
    int t = threadIdx.x;
    float4 v = *reinterpret_cast<const float4*>(&src[t * 4]);
    s.red[t] = v.x * v.x + v.y * v.y + v.z * v.z + v.w * v.w;
    __syncthreads();
    for (int o = 128; o; o >>= 1) {
        if (t < o) s.red[t] += s.red[t + o];
        __syncthreads();
    }
    float n = fmaxf(sqrtf(s.red[0]), 1e-12f);
    dst[t * 4 + 0] = 1.0f + v.x / n;
    dst[t * 4 + 1] = 1.0f + v.y / n;
    dst[t * 4 + 2] = 1.0f + v.z / n;
    dst[t * 4 + 3] = 1.0f + v.w / n;
}

// ---------------- part: fc1 GEMM (f32x2, 64x64 tile) + bias + dropout ------
__device__ void part_fc1(char* smem, int which, int n0, int m0,
                         const float* __restrict__ x,
                         const float* __restrict__ W,
                         const float* __restrict__ B,
                         float* __restrict__ out) {
    SmemFc1& s = *reinterpret_cast<SmemFc1*>(smem);
    const int tid = threadIdx.x;
    const int tx = tid % 16, ty = tid / 16;
    const int lr = tid / 4;
    const int lc = (tid % 4) * 8;
    uint64_t acc[4][2] = {};
    for (int k0 = 0; k0 < D; k0 += 32) {
        {
            const float* xr = &x[(size_t)(m0 + lr) * D + k0 + lc];
            float4 a0 = *reinterpret_cast<const float4*>(xr);
            float4 a1 = *reinterpret_cast<const float4*>(xr + 4);
            const float* wr = &W[(size_t)(n0 + lr) * D + k0 + lc];
            float4 b0 = *reinterpret_cast<const float4*>(wr);
            float4 b1 = *reinterpret_cast<const float4*>(wr + 4);
            s.As[lc + 0][lr] = a0.x; s.As[lc + 1][lr] = a0.y;
            s.As[lc + 2][lr] = a0.z; s.As[lc + 3][lr] = a0.w;
            s.As[lc + 4][lr] = a1.x; s.As[lc + 5][lr] = a1.y;
            s.As[lc + 6][lr] = a1.z; s.As[lc + 7][lr] = a1.w;
            s.Bs[lc + 0][lr] = b0.x; s.Bs[lc + 1][lr] = b0.y;
            s.Bs[lc + 2][lr] = b0.z; s.Bs[lc + 3][lr] = b0.w;
            s.Bs[lc + 4][lr] = b1.x; s.Bs[lc + 5][lr] = b1.y;
            s.Bs[lc + 6][lr] = b1.z; s.Bs[lc + 7][lr] = b1.w;
        }
        __syncthreads();
#pragma unroll
        for (int kk = 0; kk < 32; kk++) {
            float4 a = *reinterpret_cast<const float4*>(&s.As[kk][ty * 4]);
            float4 b = *reinterpret_cast<const float4*>(&s.Bs[kk][tx * 4]);
            uint64_t b01 = pack2(b.x, b.y);
            uint64_t b23 = pack2(b.z, b.w);
            uint64_t ap;
            ap = pack2(a.x, a.x); fma2(acc[0][0], ap, b01); fma2(acc[0][1], ap, b23);
            ap = pack2(a.y, a.y); fma2(acc[1][0], ap, b01); fma2(acc[1][1], ap, b23);
            ap = pack2(a.z, a.z); fma2(acc[2][0], ap, b01); fma2(acc[2][1], ap, b23);
            ap = pack2(a.w, a.w); fma2(acc[3][0], ap, b01); fma2(acc[3][1], ap, b23);
        }
        __syncthreads();
    }
    uint32_t ka, kb;
    tf2x32(0u, 42u, 0u, (uint32_t)which, ka, kb);
#pragma unroll
    for (int i = 0; i < 4; i++) {
        int b = m0 + ty * 4 + i;
#pragma unroll
        for (int jp = 0; jp < 2; jp++) {
            float2 v = unpack2(acc[i][jp]);
            int col = n0 + tx * 4 + jp * 2;
            float h0 = v.x + B[col];
            float h1 = v.y + B[col + 1];
            uint32_t i0 = (uint32_t)(b * H + col);
            out[(size_t)b * H + col]     = drop_keep(ka, kb, i0)      ? h0 / 0.8f : 0.0f;
            out[(size_t)b * H + col + 1] = drop_keep(ka, kb, i0 + 1u) ? h1 / 0.8f : 0.0f;
        }
    }
}

// ---------------- part: stream concept_proj_w once (register-resident e) ----
__device__ void part_pnd(int n, int jg,
                         const float* __restrict__ ce,
                         const float* __restrict__ W) {
    const int tid = threadIdx.x;
    const int w = tid >> 5, lane = tid & 31;
    const int jbase = jg * 64 + w * 8;
    const size_t rs = (size_t)NC * H;
    float4 ep[8], en[8];
    {
        const float* epg = ce + (size_t)n * H + lane * 4;
        const float* eng = ce + (size_t)(NC + n) * H + lane * 4;
#pragma unroll
        for (int c = 0; c < 8; c++) {
            ep[c] = *reinterpret_cast<const float4*>(&epg[c * 128]);
            en[c] = *reinterpret_cast<const float4*>(&eng[c * 128]);
        }
    }
    const float* Wr = W + (size_t)jbase * rs + (size_t)n * H + lane * 4;
#pragma unroll 1
    for (int half = 0; half < 2; half++) {
        float ap[4], an[4];
#pragma unroll 1
        for (int r = 0; r < 4; r++) {
            const float* Wp = Wr + (size_t)(half * 4 + r) * rs;
            float4 wv[8];
#pragma unroll
            for (int c = 0; c < 8; c++)
                wv[c] = *reinterpret_cast<const float4*>(&Wp[c * 128]);
            float a = 0.f, b = 0.f;
#pragma unroll
            for (int c = 0; c < 8; c++) {
                a += wv[c].x * ep[c].x + wv[c].y * ep[c].y + wv[c].z * ep[c].z + wv[c].w * ep[c].w;
                b += wv[c].x * en[c].x + wv[c].y * en[c].y + wv[c].z * en[c].z + wv[c].w * en[c].w;
            }
            ap[r] = a; an[r] = b;
        }
#pragma unroll
        for (int off = 16; off; off >>= 1) {
#pragma unroll
            for (int r = 0; r < 4; r++) {
                ap[r] += __shfl_xor_sync(0xFFFFFFFFu, ap[r], off);
                an[r] += __shfl_xor_sync(0xFFFFFFFFu, an[r], off);
            }
        }
        if (lane == 0) {
#pragma unroll
            for (int r = 0; r < 4; r++) {
                int j = jbase + half * 4 + r;
                g_pn[n * H + j] = an[r];
                g_pd[n * H + j] = ap[r] - an[r];
            }
        }
    }
}

// ---------------- part: c_proj = (bias + sum_n pn) + gt @ pd ----------------
__device__ void part_cproj(char* smem, int j0, int m0,
                           const int* __restrict__ cgt,
                           const float* __restrict__ bias) {
    SmemCp& s = *reinterpret_cast<SmemCp*>(smem);
    const int tid = threadIdx.x;
    {
        int col = j0 + (tid & 63);
        if (tid < 64) s.base[tid] = bias[col];
        __syncthreads();
        int nb = (tid >> 6) * 28;
        float part = 0.f;
#pragma unroll 4
        for (int n = nb; n < nb + 28; n++) part += g_pn[n * H + col];
        atomicAdd(&s.base[tid & 63], part);
    }
    const int tx = tid % 16, ty = tid / 16;
    float acc[4][4] = {};
    for (int k0 = 0; k0 < NC; k0 += 16) {
        __syncthreads();
        {
            int r = tid / 4;
            int c = (tid % 4) * 4;
            int b = m0 + r;
#pragma unroll
            for (int q = 0; q < 4; q++)
                s.As[c + q][r] = (cgt[(size_t)b * NC + k0 + c + q] == 1) ? 1.0f : 0.0f;
        }
        {
            int kk = tid / 16;
            int j4 = (tid % 16) * 4;
            float4 v = *reinterpret_cast<const float4*>(&g_pd[(size_t)(k0 + kk) * H + j0 + j4]);
            *reinterpret_cast<float4*>(&s.Bs[kk][j4]) = v;
        }
        __syncthreads();
#pragma unroll
        for (int kk = 0; kk < 16; kk++) {
            float4 a = *reinterpret_cast<const float4*>(&s.As[kk][ty * 4]);
            float4 b = *reinterpret_cast<const float4*>(&s.Bs[kk][tx * 4]);
            float av[4] = {a.x, a.y, a.z, a.w};
            float bv[4] = {b.x, b.y, b.z, b.w};
#pragma unroll
            for (int i = 0; i < 4; i++)
#pragma unroll
                for (int j = 0; j < 4; j++)
                    acc[i][j] = fmaf(av[i], bv[j], acc[i][j]);
        }
    }
#pragma unroll
    for (int i = 0; i < 4; i++) {
        int b = m0 + ty * 4 + i;
#pragma unroll
        for (int j = 0; j < 4; j++) {
            int col = j0 + tx * 4 + j;
            g_cproj[(size_t)b * H + col] = acc[i][j] + s.base[tx * 4 + j];
        }
    }
    // release: signal this cproj tile complete
    __threadfence();
    __syncthreads();
    if (tid == 0) atomicAdd(&g_cnt_cp, 1);
}

// ---------------- part: xy / cy energy (32 c x 16 b tile, 64-k chunks) ------
__device__ void part_xycy(char* smem, int c0, int b0,
                          const float* __restrict__ A,
                          const float* __restrict__ clsw,
                          float bias,
                          float* __restrict__ out) {
    SmemXY& s = *reinterpret_cast<SmemXY*>(smem);
    const int tid = threadIdx.x;
    const int tx = tid % 16;
    const int ty = tid / 16;
    float acc0 = 0.f, acc1 = 0.f;
    for (int k0 = 0; k0 < H; k0 += 64) {
        {
            int row = tid / 16, ko = (tid % 16) * 4;
            float4 v = *reinterpret_cast<const float4*>(&A[(size_t)(b0 + row) * H + k0 + ko]);
            s.Hs[ko + 0][row] = v.x; s.Hs[ko + 1][row] = v.y;
            s.Hs[ko + 2][row] = v.z; s.Hs[ko + 3][row] = v.w;
        }
        {
            int lr = tid / 8, lc = (tid % 8) * 4;
            int cr = c0 + lr; if (cr > C - 1) cr = C - 1;
            const float* yr = &g_y1[(size_t)cr * H + k0];
            float4 u = *reinterpret_cast<const float4*>(&yr[lc]);
            s.Ys[lc + 0][lr] = u.x; s.Ys[lc + 1][lr] = u.y;
            s.Ys[lc + 2][lr] = u.z; s.Ys[lc + 3][lr] = u.w;
            float4 u2 = *reinterpret_cast<const float4*>(&yr[32 + lc]);
            s.Ys[32 + lc + 0][lr] = u2.x; s.Ys[32 + lc + 1][lr] = u2.y;
            s.Ys[32 + lc + 2][lr] = u2.z; s.Ys[32 + lc + 3][lr] = u2.w;
        }
        if (tid < 64) s.ws[tid] = clsw[k0 + tid];
        __syncthreads();
#pragma unroll
        for (int kk = 0; kk < 64; kk++) {
            float h = s.Hs[kk][ty];
            float y0 = s.Ys[kk][tx * 2 + 0];
            float y1 = s.Ys[kk][tx * 2 + 1];
            float w = s.ws[kk];
            acc0 = fmaf(fmaxf(h * y0, 0.f), w, acc0);
            acc1 = fmaf(fmaxf(h * y1, 0.f), w, acc1);
        }
        __syncthreads();
    }
    int b = b0 + ty;
    int c = c0 + tx * 2;
    if (c < C)     out[(size_t)b * C + c]     = acc0 + bias;
    if (c + 1 < C) out[(size_t)b * C + c + 1] = acc1 + bias;
}

// ---------------- part: xc energy -------------------------------------------
__device__ void part_xc(char* smem, int n0, int b0,
                        const float* __restrict__ xcw,
                        const float* __restrict__ xcb,
                        float* __restrict__ out) {
    SmemXC& s = *reinterpret_cast<SmemXC*>(smem);
    const int tid = threadIdx.x;
    const int tx = tid % 8;
    const int ty = tid / 8;
    const int lr = tid / 8;
    const int lc = (tid % 8) * 4;
    float acc0 = 0.f, acc1 = 0.f;
    for (int k0 = 0; k0 < H; k0 += 32) {
        {
            float4 v = *reinterpret_cast<const float4*>(&g_hxc[(size_t)(b0 + lr) * H + k0 + lc]);
            s.Hs[lc + 0][lr] = v.x; s.Hs[lc + 1][lr] = v.y;
            s.Hs[lc + 2][lr] = v.z; s.Hs[lc + 3][lr] = v.w;
        }
        {
            int loc = tid / 16;
            int kk = (tid % 16) * 2;
            int nl = loc >> 1, sx = loc & 1;
            int row = sx * NC + (n0 + nl);
            float2 v = *reinterpret_cast<const float2*>(&g_c1[(size_t)row * H + k0 + kk]);
            s.Cs[kk + 0][nl * 2 + sx] = v.x;
            s.Cs[kk + 1][nl * 2 + sx] = v.y;
        }
        {
            int nl = tid / 32;
            int kk = tid % 32;
            s.Ws[kk][nl] = xcw[(size_t)(n0 + nl) * H + k0 + kk];
        }
        __syncthreads();
#pragma unroll
        for (int kk = 0; kk < 32; kk++) {
            float h = s.Hs[kk][ty];
            float w = s.Ws[kk][tx];
            float cp = s.Cs[kk][tx * 2 + 0];
            float cn = s.Cs[kk][tx * 2 + 1];
            acc0 = fmaf(fmaxf(h * cp, 0.f), w, acc0);
            acc1 = fmaf(fmaxf(h * cn, 0.f), w, acc1);
        }
        __syncthreads();
    }
    int b = b0 + ty, n = n0 + tx;
    float bb = xcb[n];
    size_t base = (size_t)(2 * BS * C) + (size_t)b * (NC * 2) + n * 2;
    out[base + 0] = acc0 + bb;
    out[base + 1] = acc1 + bb;
}

// ================= launch 1: fc1 + norm + pnd (overlapped) ==================
#define L1_FC1   128
#define L1_NORM  (C + 2 * NC)                 // 424
#define L1_PND   (NC * 16)                    // 1792 (64-j groups)
#define L1_GRID  (L1_FC1 + L1_NORM + L1_PND)

__global__ __launch_bounds__(256, 2) void k_main(const float* __restrict__ x,
                                                 const float* __restrict__ ye,
                                                 const float* __restrict__ ce,
                                                 const float* __restrict__ w0,
                                                 const float* __restrict__ b0,
                                                 const float* __restrict__ w1,
                                                 const float* __restrict__ b1,
                                                 const float* __restrict__ cpw) {
    __shared__ __align__(16) char smem[SMEM_BYTES];
    int bid = blockIdx.x;
    if (bid == 0 && threadIdx.x == 0) g_cnt_cp = 0;   // reset gate (next launch reads)
    if (bid < L1_FC1) {
        int which = bid >> 6;
        int rem = bid & 63;
        part_fc1(smem, which, (rem % 16) * 64, (rem / 16) * 64, x,
                 which ? w1 : w0, which ? b1 : b0, which ? g_hxc : g_hxy);
    } else if (bid < L1_FC1 + L1_NORM) {
        part_norm(smem, bid - L1_FC1, ye, ce);
    } else {
        int p = bid - (L1_FC1 + L1_NORM);
        part_pnd(p % NC, p / NC, ce, cpw);
    }
}

// ====== launch 2: cproj + xy + xc + cy (cy gated by nanosleep poll) =========
#define L2_CP   (16 * 4)              // 64  (wave-1 resident: no deadlock)
#define L2_XY   112                   // 7 x 16
#define L2_XC   112                   // 14 x 8
#define L2_CY   112                   // 7 x 16
#define L2_GRID (L2_CP + L2_XY + L2_XC + L2_CY)   // 400

__global__ __launch_bounds__(256) void k_ep(const int* __restrict__ cgt,
                                            const float* __restrict__ cpb,
                                            const float* __restrict__ clsxy_w,
                                            const float* __restrict__ clsxy_b,
                                            const float* __restrict__ clscy_w,
                                            const float* __restrict__ clscy_b,
                                            const float* __restrict__ xcw,
                                            const float* __restrict__ xcb,
                                            float* __restrict__ out) {
    __shared__ __align__(16) char smem[SMEM_BYTES];
    int bid = blockIdx.x;
    if (bid < L2_CP) {
        part_cproj(smem, (bid % 16) * 64, (bid / 16) * 64, cgt, cpb);
    } else if (bid < L2_CP + L2_XY) {
        int p = bid - L2_CP;
        part_xycy(smem, (p % 7) * 32, (p / 7) * 16, g_hxy, clsxy_w, clsxy_b[0], out);
    } else if (bid < L2_CP + L2_XY + L2_XC) {
        int p = bid - (L2_CP + L2_XY);
        part_xc(smem, (p % 14) * 8, (p / 14) * 32, xcw, xcb, out);
    } else {
        int p = bid - (L2_CP + L2_XY + L2_XC);
        // gentle gate: nanosleep poll until all 64 cproj tiles published
        if (threadIdx.x == 0) {
            volatile int* cnt = &g_cnt_cp;
            while (*cnt < L2_CP) __nanosleep(128);
        }
        __syncthreads();
        __threadfence();
        part_xycy(smem, (p % 7) * 32, (p / 7) * 16, g_cproj, clscy_w, clscy_b[0],
                  out + (size_t)BS * C);
    }
}

// ---------------- launch ----------------------------------------------------
extern "C" void kernel_launch(void* const* d_in, const int* in_sizes, int n_in,
                              void* d_out, int out_size) {
    (void)in_sizes; (void)n_in; (void)out_size;
    const float* x       = (const float*)d_in[0];
    const int*   c_gt    = (const int*)d_in[1];
    const float* y_emb   = (const float*)d_in[2];
    const float* c_emb   = (const float*)d_in[3];
    const float* xy_w    = (const float*)d_in[4];
    const float* xy_b    = (const float*)d_in[5];
    const float* xc_w1   = (const float*)d_in[6];
    const float* xc_b1   = (const float*)d_in[7];
    const float* clsxy_w = (const float*)d_in[8];
    const float* clsxy_b = (const float*)d_in[9];
    const float* clscy_w = (const float*)d_in[10];
    const float* clscy_b = (const float*)d_in[11];
    const float* xcw     = (const float*)d_in[12];
    const float* xcb     = (const float*)d_in[13];
    const float* cpw     = (const float*)d_in[14];
    const float* cpb     = (const float*)d_in[15];
    float* out = (float*)d_out;

    k_main<<<L1_GRID, 256>>>(x, y_emb, c_emb, xy_w, xy_b, xc_w1, xc_b1, cpw);
    k_ep<<<L2_GRID, 256>>>(c_gt, cpb, clsxy_w, clsxy_b, clscy_w, clscy_b,
                           xcw, xcb, out);
}